// round 6
// baseline (speedup 1.0000x reference)
#include <cuda_runtime.h>
#include <cstdint>
#include <cstddef>

// ---------------- scratch (tf32-rounded weights) ----------------
__device__ float g_W1[2048 * 160];
__device__ float g_W2[5 * 32 * 2048];

__device__ __forceinline__ unsigned f2tf32(float f) {
    unsigned u;
    asm("cvt.rna.tf32.f32 %0, %1;" : "=r"(u) : "f"(f));
    return u;
}

__device__ __forceinline__ void mma_tf32(float c[4], const unsigned a[4],
                                         unsigned b0, unsigned b1) {
    asm volatile(
        "mma.sync.aligned.m16n8k8.row.col.f32.tf32.tf32.f32 "
        "{%0,%1,%2,%3}, {%4,%5,%6,%7}, {%8,%9}, {%0,%1,%2,%3};\n"
        : "+f"(c[0]), "+f"(c[1]), "+f"(c[2]), "+f"(c[3])
        : "r"(a[0]), "r"(a[1]), "r"(a[2]), "r"(a[3]), "r"(b0), "r"(b1));
}

__device__ __forceinline__ void cp16(uint32_t dst, const void* src) {
    asm volatile("cp.async.cg.shared.global [%0], [%1], 16;\n" :: "r"(dst), "l"(src));
}
__device__ __forceinline__ void cp_commit() { asm volatile("cp.async.commit_group;\n"); }
__device__ __forceinline__ void cp_wait0()  { asm volatile("cp.async.wait_group 0;\n" ::: "memory"); }
__device__ __forceinline__ void cp_wait1()  { asm volatile("cp.async.wait_group 1;\n" ::: "memory"); }

__device__ __forceinline__ uint32_t smem_u32(const void* p) {
    return (uint32_t)__cvta_generic_to_shared(p);
}

// ---------------- smem layout (bytes) ----------------
// persistent:   Hs   [64][164] u32          @ 0       (41984)
// phase 1:      As   [2][64][36] u32        @ 41984   (18432)
//               Bs1  [3][32][168] u32       @ 60416   (64512)
//               Xs   [3][65][36] f32        @ 124928  (28080)
//               tmxs [2048] f32             @ 153008  (8192)   -> end 161200
// phase 2:      Bs2  [3][32][136] u32       @ 41984   (52224)
//               Xv   [2][65][132] f32       @ 94208   (68640)  -> end 162848
#define SM_TOTAL 163840
#define OFF_HS   0
#define OFF_AS   41984
#define OFF_BS1  60416
#define OFF_XS   124928
#define OFF_TMX  153008
#define OFF_BS2  41984
#define OFF_XV   94208

__global__ void __launch_bounds__(256)
fused_kernel(const float* __restrict__ x, const float* __restrict__ state,
             const float* __restrict__ tmx,
             const float* __restrict__ mk, const float* __restrict__ mw,
             const float* __restrict__ mv, const float* __restrict__ mr,
             const float* __restrict__ mg,
             const int* __restrict__ ip, float* __restrict__ out,
             int S, int D, int srows)
{
    extern __shared__ unsigned char sm[];
    unsigned (*Hs)[164]      = reinterpret_cast<unsigned (*)[164]>(sm + OFF_HS);
    unsigned (*As)[64][36]   = reinterpret_cast<unsigned (*)[64][36]>(sm + OFF_AS);
    unsigned (*Bs1)[32][168] = reinterpret_cast<unsigned (*)[32][168]>(sm + OFF_BS1);
    float    (*Xs)[65][36]   = reinterpret_cast<float (*)[65][36]>(sm + OFF_XS);
    float*    tmxs           = reinterpret_cast<float*>(sm + OFF_TMX);
    unsigned (*Bs2)[32][136] = reinterpret_cast<unsigned (*)[32][136]>(sm + OFF_BS2);
    float    (*Xv)[65][132]  = reinterpret_cast<float (*)[65][132]>(sm + OFF_XV);

    const int tid  = threadIdx.x;
    const int lane = tid & 31;
    const int warp = tid >> 5;
    const int wm   = warp & 1;
    const int wn   = warp >> 1;
    const int gid  = lane >> 2;
    const int tg   = lane & 3;
    const int m0   = blockIdx.x * 64;
    const int i1   = srows * ip[0] + 1;

    // source for the "previous token" boundary row (local row -1 of this strip)
    const float* xprow0 = ((m0 % S) == 0)
        ? state + ((size_t)(m0 / S) * srows + i1) * D
        : x + (size_t)(m0 - 1) * D;

    // ======================= PHASE 1 =======================
    auto issueX1 = [&](int s) {
        int k0 = s * 32, slot = s % 3;
        #pragma unroll
        for (int it = 0; it < 2; it++) {
            int u = tid + it * 256;
            int r = u >> 3, cg = (u & 7) * 4;
            const float* src = (r == 0) ? xprow0 + k0 + cg
                                        : x + (size_t)(m0 - 1 + r) * D + k0 + cg;
            cp16(smem_u32(&Xs[slot][r][cg]), src);
        }
        if (tid < 8) {
            int cg = tid * 4;
            cp16(smem_u32(&Xs[slot][64][cg]), x + (size_t)(m0 + 63) * D + k0 + cg);
        }
    };
    auto issueB1 = [&](int s) {
        int k0 = s * 32, slot = s % 3;
        #pragma unroll
        for (int it = 0; it < 5; it++) {
            int e = tid + it * 256;
            int r = e / 40, c4 = (e % 40) * 4;
            cp16(smem_u32(&Bs1[slot][r][c4]), g_W1 + (size_t)(k0 + r) * 160 + c4);
        }
    };

    // preload tmx + stages 0,1
    #pragma unroll
    for (int it = 0; it < 2; it++) {
        int e = tid + it * 256;
        if (e < D / 4) cp16(smem_u32(tmxs + e * 4), tmx + e * 4);
    }
    issueX1(0); issueB1(0); cp_commit();
    issueX1(1); issueB1(1); cp_commit();

    float acc1[2][5][4];
    #pragma unroll
    for (int a = 0; a < 2; a++)
        #pragma unroll
        for (int b = 0; b < 5; b++)
            #pragma unroll
            for (int c = 0; c < 4; c++) acc1[a][b][c] = 0.f;

    const int nkt = D / 32;
    for (int kt = 0; kt < nkt; kt++) {
        const int slot = kt % 3, buf = kt & 1, k0 = kt * 32;
        if (kt + 1 < nkt) cp_wait1(); else cp_wait0();
        __syncthreads();
        if (kt + 2 < nkt) { issueX1(kt + 2); issueB1(kt + 2); cp_commit(); }

        // convert: mixed tf32 A tile from staged x/xprev/tmx
        #pragma unroll
        for (int it = 0; it < 2; it++) {
            int e = tid + it * 256;
            int r = e >> 3, c4 = (e & 7) * 4;
            float4 xv = *reinterpret_cast<float4*>(&Xs[slot][r + 1][c4]);
            float4 xp = *reinterpret_cast<float4*>(&Xs[slot][r][c4]);
            float4 tv = *reinterpret_cast<float4*>(&tmxs[k0 + c4]);
            uint4 o;
            o.x = f2tf32(xv.x + (xp.x - xv.x) * tv.x);
            o.y = f2tf32(xv.y + (xp.y - xv.y) * tv.y);
            o.z = f2tf32(xv.z + (xp.z - xv.z) * tv.z);
            o.w = f2tf32(xv.w + (xp.w - xv.w) * tv.w);
            *reinterpret_cast<uint4*>(&As[buf][r][c4]) = o;
        }
        __syncthreads();

        #pragma unroll
        for (int kk = 0; kk < 4; kk++) {
            unsigned a[2][4];
            #pragma unroll
            for (int mi = 0; mi < 2; mi++) {
                int ar = wm * 32 + mi * 16 + gid;
                int ac = kk * 8 + tg;
                a[mi][0] = As[buf][ar][ac];
                a[mi][1] = As[buf][ar + 8][ac];
                a[mi][2] = As[buf][ar][ac + 4];
                a[mi][3] = As[buf][ar + 8][ac + 4];
            }
            #pragma unroll
            for (int nt = 0; nt < 5; nt++) {
                int bc = wn * 40 + nt * 8 + gid;
                unsigned b0 = Bs1[slot][kk * 8 + tg][bc];
                unsigned b1 = Bs1[slot][kk * 8 + tg + 4][bc];
                mma_tf32(acc1[0][nt], a[0], b0, b1);
                mma_tf32(acc1[1][nt], a[1], b0, b1);
            }
        }
    }

    __syncthreads();   // all phase-1 smem reads done before phase-2 cp.async aliases it

    // epilogue: tanh -> tf32 bits -> Hs (stays in smem)
    #pragma unroll
    for (int mi = 0; mi < 2; mi++)
        #pragma unroll
        for (int nt = 0; nt < 5; nt++) {
            int gc = wn * 40 + nt * 8 + 2 * tg;
            #pragma unroll
            for (int h = 0; h < 2; h++) {
                int lr = wm * 32 + mi * 16 + gid + h * 8;
                Hs[lr][gc]     = f2tf32(tanhf(acc1[mi][nt][2 * h]));
                Hs[lr][gc + 1] = f2tf32(tanhf(acc1[mi][nt][2 * h + 1]));
            }
        }

    // ======================= PHASE 2 =======================
    auto issueB2 = [&](int t) {
        int n0 = (t / 5) * 128, f = t % 5, slot = t % 3;
        #pragma unroll
        for (int it = 0; it < 4; it++) {
            int e = tid + it * 256;
            int r = e >> 5, c4 = (e & 31) * 4;
            cp16(smem_u32(&Bs2[slot][r][c4]), g_W2 + ((size_t)f * 32 + r) * D + n0 + c4);
        }
    };
    auto issueXv = [&](int n) {
        int n0 = n * 128, slot = n & 1;
        #pragma unroll
        for (int it = 0; it < 8; it++) {
            int u = tid + it * 256;
            int r = u >> 5, cg = (u & 31) * 4;
            const float* src = (r == 0) ? xprow0 + n0 + cg
                                        : x + (size_t)(m0 - 1 + r) * D + n0 + cg;
            cp16(smem_u32(&Xv[slot][r][cg]), src);
        }
        if (tid < 32) {
            int cg = tid * 4;
            cp16(smem_u32(&Xv[slot][64][cg]), x + (size_t)(m0 + 63) * D + n0 + cg);
        }
    };

    issueB2(0); issueXv(0); cp_commit();
    issueB2(1); cp_commit();

    const int nt2 = (D / 128) * 5;
    for (int t = 0; t < nt2; t++) {
        const int n = t / 5, f = t - n * 5, slot = t % 3, xslot = n & 1, n0 = n * 128;
        if (t + 1 < nt2) cp_wait1(); else cp_wait0();
        __syncthreads();
        if (t + 2 < nt2) {
            issueB2(t + 2);
            if ((t + 2) % 5 == 0) issueXv((t + 2) / 5);
            cp_commit();
        }

        float acc[2][4][4];
        #pragma unroll
        for (int a = 0; a < 2; a++)
            #pragma unroll
            for (int b = 0; b < 4; b++)
                #pragma unroll
                for (int c = 0; c < 4; c++) acc[a][b][c] = 0.f;

        #pragma unroll
        for (int kk = 0; kk < 4; kk++) {
            unsigned a[2][4];
            #pragma unroll
            for (int mi = 0; mi < 2; mi++) {
                int ar = wm * 32 + mi * 16 + gid;
                int ac = f * 32 + kk * 8 + tg;
                a[mi][0] = Hs[ar][ac];
                a[mi][1] = Hs[ar + 8][ac];
                a[mi][2] = Hs[ar][ac + 4];
                a[mi][3] = Hs[ar + 8][ac + 4];
            }
            #pragma unroll
            for (int nt = 0; nt < 4; nt++) {
                int bc = wn * 32 + nt * 8 + gid;
                unsigned b0 = Bs2[slot][kk * 8 + tg][bc];
                unsigned b1 = Bs2[slot][kk * 8 + tg + 4][bc];
                mma_tf32(acc[0][nt], a[0], b0, b1);
                mma_tf32(acc[1][nt], a[1], b0, b1);
            }
        }

        const float* maa = (f == 0) ? mk : (f == 1) ? mw : (f == 2) ? mv : (f == 3) ? mr : mg;

        #pragma unroll
        for (int mi = 0; mi < 2; mi++)
            #pragma unroll
            for (int nt = 0; nt < 4; nt++) {
                int lc = wn * 32 + nt * 8 + 2 * tg;
                int gc = n0 + lc;
                float2 mm = *reinterpret_cast<const float2*>(maa + gc);
                #pragma unroll
                for (int h = 0; h < 2; h++) {
                    int lr = wm * 32 + mi * 16 + gid + h * 8;
                    float2 xv = *reinterpret_cast<float2*>(&Xv[xslot][lr + 1][lc]);
                    float2 xp = *reinterpret_cast<float2*>(&Xv[xslot][lr][lc]);
                    float y0 = acc[mi][nt][2 * h];
                    float y1 = acc[mi][nt][2 * h + 1];
                    float2 o;
                    o.x = xv.x + (xp.x - xv.x) * (mm.x + y0);
                    o.y = xv.y + (xp.y - xv.y) * (mm.y + y1);
                    __stcs(reinterpret_cast<float2*>(
                        out + ((size_t)(m0 + lr) * 5 + f) * D + gc), o);
                }
            }
    }
}

// ---------------------------------------------------------------------------
// prep kernel: tf32-round W1/W2 + build new_state, one launch
// ---------------------------------------------------------------------------
__global__ void prep_kernel(const float* __restrict__ w1, const float* __restrict__ w2,
                            const float* __restrict__ x, const float* __restrict__ state,
                            const int* __restrict__ ip, float* __restrict__ outs,
                            int n1, int n2, int nb1, int S, int D, int srows, int total)
{
    int bid = blockIdx.x;
    if (bid < nb1) {
        int idx = (bid * 256 + threadIdx.x) * 4;
        if (idx < n1) {
            float4 v = *reinterpret_cast<const float4*>(w1 + idx);
            float4 o;
            o.x = __uint_as_float(f2tf32(v.x)); o.y = __uint_as_float(f2tf32(v.y));
            o.z = __uint_as_float(f2tf32(v.z)); o.w = __uint_as_float(f2tf32(v.w));
            *reinterpret_cast<float4*>(g_W1 + idx) = o;
        }
        if (idx < n2) {
            float4 v = *reinterpret_cast<const float4*>(w2 + idx);
            float4 o;
            o.x = __uint_as_float(f2tf32(v.x)); o.y = __uint_as_float(f2tf32(v.y));
            o.z = __uint_as_float(f2tf32(v.z)); o.w = __uint_as_float(f2tf32(v.w));
            *reinterpret_cast<float4*>(g_W2 + idx) = o;
        }
    } else {
        int idx = ((bid - nb1) * 256 + threadIdx.x) * 4;
        if (idx < total) {
            int i1 = srows * ip[0] + 1;
            int d = idx % D;
            int r = (idx / D) % srows;
            int b = idx / (D * srows);
            float4 v;
            if (r == i1)
                v = *reinterpret_cast<const float4*>(x + ((size_t)b * S + (S - 1)) * D + d);
            else
                v = *reinterpret_cast<const float4*>(state + idx);
            *reinterpret_cast<float4*>(outs + idx) = v;
        }
    }
}

extern "C" void kernel_launch(void* const* d_in, const int* in_sizes, int n_in,
                              void* d_out, int out_size)
{
    const float* x     = (const float*)d_in[0];
    const float* state = (const float*)d_in[1];
    const float* tmx   = (const float*)d_in[2];
    const float* w1    = (const float*)d_in[3];
    const float* w2    = (const float*)d_in[4];
    const float* mk    = (const float*)d_in[5];
    const float* mw    = (const float*)d_in[6];
    const float* mv    = (const float*)d_in[7];
    const float* mr    = (const float*)d_in[8];
    const float* mg    = (const float*)d_in[9];
    const int*   ip    = (const int*)d_in[10];
    float* out = (float*)d_out;

    const int D     = in_sizes[2];
    const int srows = 2 + D / 32;
    const int Bb    = in_sizes[1] / (srows * D);
    const int M     = in_sizes[0] / D;
    const int S     = M / Bb;
    const int n1    = in_sizes[3];
    const int n2    = in_sizes[4];

    static bool attr_done = false;
    if (!attr_done) {
        cudaFuncSetAttribute(fused_kernel, cudaFuncAttributeMaxDynamicSharedMemorySize, SM_TOTAL);
        attr_done = true;
    }

    long long main_sz = (long long)M * 5 * D;
    long long st_sz   = (long long)Bb * srows * D;
    int total = ((long long)out_size >= main_sz + st_sz) ? (int)st_sz : 0;

    int nmax = n1 > n2 ? n1 : n2;
    int nb1 = (nmax / 4 + 255) / 256;
    int nb2 = (total / 4 + 255) / 256;
    prep_kernel<<<nb1 + nb2, 256>>>(w1, w2, x, state, ip, out + main_sz,
                                    n1, n2, nb1, S, D, srows, total);
    fused_kernel<<<M / 64, 256, SM_TOTAL>>>(x, state, tmx, mk, mw, mv, mr, mg,
                                            ip, out, S, D, srows);
}

// round 7
// speedup vs baseline: 1.1435x; 1.1435x over previous
#include <cuda_runtime.h>
#include <cstdint>
#include <cstddef>

// ---------------- scratch ----------------
__device__ float g_W1[2048 * 160];      // tf32-rounded w1
__device__ float g_W2[5 * 32 * 2048];   // tf32-rounded w2
__device__ float g_H[8192 * 160];       // tanh(xx@W1), tf32-rounded

__device__ __forceinline__ unsigned f2tf32(float f) {
    unsigned u;
    asm("cvt.rna.tf32.f32 %0, %1;" : "=r"(u) : "f"(f));
    return u;
}

__device__ __forceinline__ void mma_tf32(float c[4], const unsigned a[4],
                                         unsigned b0, unsigned b1) {
    asm volatile(
        "mma.sync.aligned.m16n8k8.row.col.f32.tf32.tf32.f32 "
        "{%0,%1,%2,%3}, {%4,%5,%6,%7}, {%8,%9}, {%0,%1,%2,%3};\n"
        : "+f"(c[0]), "+f"(c[1]), "+f"(c[2]), "+f"(c[3])
        : "r"(a[0]), "r"(a[1]), "r"(a[2]), "r"(a[3]), "r"(b0), "r"(b1));
}

__device__ __forceinline__ void cp16(uint32_t dst, const void* src) {
    asm volatile("cp.async.cg.shared.global [%0], [%1], 16;\n" :: "r"(dst), "l"(src));
}
__device__ __forceinline__ void cp_commit() { asm volatile("cp.async.commit_group;\n"); }
__device__ __forceinline__ void cp_wait0()  { asm volatile("cp.async.wait_group 0;\n" ::: "memory"); }
__device__ __forceinline__ void cp_wait1()  { asm volatile("cp.async.wait_group 1;\n" ::: "memory"); }

__device__ __forceinline__ uint32_t smem_u32(const void* p) {
    return (uint32_t)__cvta_generic_to_shared(p);
}

// ============================================================================
// GEMM1: H[M,160] = tanh( (x + sx*tmx) @ W1[D,160] )
// 512 threads, 16 warps 4(m)x4(n), warp tile 16x40. Block tile 64x160.
// 3-stage cp.async ring for x rows and W1 K-tiles; mix done smem->smem.
// ============================================================================
#define G1_AS   18432                    // 2*64*36*4
#define G1_BS   64512                    // 3*32*168*4
#define G1_XS   28080                    // 3*65*36*4
#define G1_TMX  8192
#define G1_SMEM (G1_AS + G1_BS + G1_XS + G1_TMX)

__global__ void __launch_bounds__(512)
gemm1_kernel(const float* __restrict__ x, const float* __restrict__ state,
             const float* __restrict__ tmx,
             const int* __restrict__ ip, int S, int D, int srows)
{
    extern __shared__ unsigned char sm[];
    unsigned (*As)[64][36]   = reinterpret_cast<unsigned (*)[64][36]>(sm);
    unsigned (*Bs1)[32][168] = reinterpret_cast<unsigned (*)[32][168]>(sm + G1_AS);
    float    (*Xs)[65][36]   = reinterpret_cast<float (*)[65][36]>(sm + G1_AS + G1_BS);
    float*    tmxs           = reinterpret_cast<float*>(sm + G1_AS + G1_BS + G1_XS);

    const int tid  = threadIdx.x;
    const int lane = tid & 31;
    const int warp = tid >> 5;
    const int wm   = warp & 3;    // rows wm*16
    const int wn   = warp >> 2;   // cols wn*40
    const int gid  = lane >> 2;
    const int tg   = lane & 3;
    const int m0   = blockIdx.x * 64;
    const int i1   = srows * ip[0] + 1;

    const float* xprow0 = ((m0 % S) == 0)
        ? state + ((size_t)(m0 / S) * srows + i1) * D
        : x + (size_t)(m0 - 1) * D;

    auto issueX1 = [&](int s) {
        int k0 = s * 32, slot = s % 3;
        {
            int r = tid >> 3, cg = (tid & 7) * 4;
            const float* src = (r == 0) ? xprow0 + k0 + cg
                                        : x + (size_t)(m0 - 1 + r) * D + k0 + cg;
            cp16(smem_u32(&Xs[slot][r][cg]), src);
        }
        if (tid < 8) {
            int cg = tid * 4;
            cp16(smem_u32(&Xs[slot][64][cg]), x + (size_t)(m0 + 63) * D + k0 + cg);
        }
    };
    auto issueB1 = [&](int s) {
        int k0 = s * 32, slot = s % 3;
        #pragma unroll
        for (int it = 0; it < 3; it++) {
            int e = tid + it * 512;
            if (e < 1280) {
                int r = e / 40, c4 = (e % 40) * 4;
                cp16(smem_u32(&Bs1[slot][r][c4]), g_W1 + (size_t)(k0 + r) * 160 + c4);
            }
        }
    };

    if (tid < D / 4) cp16(smem_u32(tmxs + tid * 4), tmx + tid * 4);
    issueX1(0); issueB1(0); cp_commit();
    issueX1(1); issueB1(1); cp_commit();

    float acc1[5][4];
    #pragma unroll
    for (int b = 0; b < 5; b++)
        #pragma unroll
        for (int c = 0; c < 4; c++) acc1[b][c] = 0.f;

    const int nkt = D / 32;
    for (int kt = 0; kt < nkt; kt++) {
        const int slot = kt % 3, buf = kt & 1, k0 = kt * 32;
        if (kt + 1 < nkt) cp_wait1(); else cp_wait0();
        __syncthreads();
        if (kt + 2 < nkt) { issueX1(kt + 2); issueB1(kt + 2); cp_commit(); }

        // mix -> tf32 A tile
        {
            int r = tid >> 3, c4 = (tid & 7) * 4;
            float4 xv = *reinterpret_cast<float4*>(&Xs[slot][r + 1][c4]);
            float4 xp = *reinterpret_cast<float4*>(&Xs[slot][r][c4]);
            float4 tv = *reinterpret_cast<float4*>(&tmxs[k0 + c4]);
            uint4 o;
            o.x = f2tf32(xv.x + (xp.x - xv.x) * tv.x);
            o.y = f2tf32(xv.y + (xp.y - xv.y) * tv.y);
            o.z = f2tf32(xv.z + (xp.z - xv.z) * tv.z);
            o.w = f2tf32(xv.w + (xp.w - xv.w) * tv.w);
            *reinterpret_cast<uint4*>(&As[buf][r][c4]) = o;
        }
        __syncthreads();

        #pragma unroll
        for (int kk = 0; kk < 4; kk++) {
            unsigned a[4];
            int ar = wm * 16 + gid;
            int ac = kk * 8 + tg;
            a[0] = As[buf][ar][ac];
            a[1] = As[buf][ar + 8][ac];
            a[2] = As[buf][ar][ac + 4];
            a[3] = As[buf][ar + 8][ac + 4];
            #pragma unroll
            for (int nt = 0; nt < 5; nt++) {
                int bc = wn * 40 + nt * 8 + gid;
                unsigned b0 = Bs1[slot][kk * 8 + tg][bc];
                unsigned b1 = Bs1[slot][kk * 8 + tg + 4][bc];
                mma_tf32(acc1[nt], a, b0, b1);
            }
        }
    }

    // epilogue: tanh -> tf32 -> g_H
    #pragma unroll
    for (int nt = 0; nt < 5; nt++) {
        int gc = wn * 40 + nt * 8 + 2 * tg;
        #pragma unroll
        for (int h = 0; h < 2; h++) {
            int gr = m0 + wm * 16 + gid + h * 8;
            float2 v;
            v.x = __uint_as_float(f2tf32(tanhf(acc1[nt][2 * h])));
            v.y = __uint_as_float(f2tf32(tanhf(acc1[nt][2 * h + 1])));
            *reinterpret_cast<float2*>(g_H + (size_t)gr * 160 + gc) = v;
        }
    }
}

// ============================================================================
// GEMM2 + epilogue. Block = (m-tile 64) x (n-tile 128), loops 5 modes.
// H tile + x tile loaded once per CTA; W2 double-buffered.
// 256 threads, __launch_bounds__(256,2) -> 2 CTAs/SM (111 KB smem each).
// ============================================================================
#define G2_AS   41984                    // 64*164*4
#define G2_BS   34816                    // 2*32*136*4
#define G2_XV   34320                    // 65*132*4
#define G2_SMEM (G2_AS + G2_BS + G2_XV)

__global__ void __launch_bounds__(256, 2)
gemm2_kernel(const float* __restrict__ x, const float* __restrict__ state,
             const float* __restrict__ mk, const float* __restrict__ mw,
             const float* __restrict__ mv, const float* __restrict__ mr,
             const float* __restrict__ mg,
             const int* __restrict__ ip, float* __restrict__ out,
             int S, int D, int srows)
{
    extern __shared__ unsigned char sm[];
    unsigned (*As)[164]     = reinterpret_cast<unsigned (*)[164]>(sm);
    unsigned (*Bs2)[32][136]= reinterpret_cast<unsigned (*)[32][136]>(sm + G2_AS);
    float    (*Xv)[132]     = reinterpret_cast<float (*)[132]>(sm + G2_AS + G2_BS);

    const int tid  = threadIdx.x;
    const int lane = tid & 31;
    const int warp = tid >> 5;
    const int wm   = warp & 1;
    const int wn   = warp >> 1;
    const int gid  = lane >> 2;
    const int tg   = lane & 3;
    const int m0   = blockIdx.x * 64;
    const int n0   = blockIdx.y * 128;
    const int i1   = srows * ip[0] + 1;

    const float* xprow0 = ((m0 % S) == 0)
        ? state + ((size_t)(m0 / S) * srows + i1) * D
        : x + (size_t)(m0 - 1) * D;

    auto cpB2 = [&](int f, int slot) {
        #pragma unroll
        for (int it = 0; it < 4; it++) {
            int e = tid + it * 256;
            int r = e >> 5, c4 = (e & 31) * 4;
            cp16(smem_u32(&Bs2[slot][r][c4]), g_W2 + ((size_t)f * 32 + r) * D + n0 + c4);
        }
    };

    // prologue: H tile (all 160 cols), x tile, B2(0) | B2(1)
    #pragma unroll
    for (int it = 0; it < 10; it++) {
        int e = tid + it * 256;
        int r = e / 40, c4 = (e % 40) * 4;
        cp16(smem_u32(&As[r][c4]), g_H + (size_t)(m0 + r) * 160 + c4);
    }
    #pragma unroll
    for (int it = 0; it < 8; it++) {
        int u = tid + it * 256;
        int r = u >> 5, cg = (u & 31) * 4;
        const float* src = (r == 0) ? xprow0 + n0 + cg
                                    : x + (size_t)(m0 - 1 + r) * D + n0 + cg;
        cp16(smem_u32(&Xv[r][cg]), src);
    }
    if (tid < 32) {
        int cg = tid * 4;
        cp16(smem_u32(&Xv[64][cg]), x + (size_t)(m0 + 63) * D + n0 + cg);
    }
    cpB2(0, 0);
    cp_commit();
    cpB2(1, 1);
    cp_commit();

    for (int f = 0; f < 5; f++) {
        const int slot = f & 1;
        if (f < 4) cp_wait1(); else cp_wait0();
        __syncthreads();

        float acc[2][4][4];
        #pragma unroll
        for (int a = 0; a < 2; a++)
            #pragma unroll
            for (int b = 0; b < 4; b++)
                #pragma unroll
                for (int c = 0; c < 4; c++) acc[a][b][c] = 0.f;

        #pragma unroll
        for (int kk = 0; kk < 4; kk++) {
            unsigned a[2][4];
            #pragma unroll
            for (int mi = 0; mi < 2; mi++) {
                int ar = wm * 32 + mi * 16 + gid;
                int ac = f * 32 + kk * 8 + tg;
                a[mi][0] = As[ar][ac];
                a[mi][1] = As[ar + 8][ac];
                a[mi][2] = As[ar][ac + 4];
                a[mi][3] = As[ar + 8][ac + 4];
            }
            #pragma unroll
            for (int nt = 0; nt < 4; nt++) {
                int bc = wn * 32 + nt * 8 + gid;
                unsigned b0 = Bs2[slot][kk * 8 + tg][bc];
                unsigned b1 = Bs2[slot][kk * 8 + tg + 4][bc];
                mma_tf32(acc[0][nt], a[0], b0, b1);
                mma_tf32(acc[1][nt], a[1], b0, b1);
            }
        }
        __syncthreads();           // all warps done reading Bs2[slot]
        if (f + 2 <= 4) {          // refill this slot for mode f+2
            cpB2(f + 2, slot);
            cp_commit();
        }

        const float* maa = (f == 0) ? mk : (f == 1) ? mw : (f == 2) ? mv
                         : (f == 3) ? mr : mg;

        #pragma unroll
        for (int mi = 0; mi < 2; mi++)
            #pragma unroll
            for (int nt = 0; nt < 4; nt++) {
                int lc = wn * 32 + nt * 8 + 2 * tg;
                int gc = n0 + lc;
                float2 mm = *reinterpret_cast<const float2*>(maa + gc);
                #pragma unroll
                for (int h = 0; h < 2; h++) {
                    int lr = wm * 32 + mi * 16 + gid + h * 8;
                    float2 xv = *reinterpret_cast<float2*>(&Xv[lr + 1][lc]);
                    float2 xp = *reinterpret_cast<float2*>(&Xv[lr][lc]);
                    float y0 = acc[mi][nt][2 * h];
                    float y1 = acc[mi][nt][2 * h + 1];
                    float2 o;
                    o.x = xv.x + (xp.x - xv.x) * (mm.x + y0);
                    o.y = xv.y + (xp.y - xv.y) * (mm.y + y1);
                    __stcs(reinterpret_cast<float2*>(
                        out + ((size_t)(m0 + lr) * 5 + f) * D + gc), o);
                }
            }
    }
}

// ---------------------------------------------------------------------------
// prep kernel: tf32-round W1/W2 + build new_state
// ---------------------------------------------------------------------------
__global__ void prep_kernel(const float* __restrict__ w1, const float* __restrict__ w2,
                            const float* __restrict__ x, const float* __restrict__ state,
                            const int* __restrict__ ip, float* __restrict__ outs,
                            int n1, int n2, int nb1, int S, int D, int srows, int total)
{
    int bid = blockIdx.x;
    if (bid < nb1) {
        int idx = (bid * 256 + threadIdx.x) * 4;
        if (idx < n1) {
            float4 v = *reinterpret_cast<const float4*>(w1 + idx);
            float4 o;
            o.x = __uint_as_float(f2tf32(v.x)); o.y = __uint_as_float(f2tf32(v.y));
            o.z = __uint_as_float(f2tf32(v.z)); o.w = __uint_as_float(f2tf32(v.w));
            *reinterpret_cast<float4*>(g_W1 + idx) = o;
        }
        if (idx < n2) {
            float4 v = *reinterpret_cast<const float4*>(w2 + idx);
            float4 o;
            o.x = __uint_as_float(f2tf32(v.x)); o.y = __uint_as_float(f2tf32(v.y));
            o.z = __uint_as_float(f2tf32(v.z)); o.w = __uint_as_float(f2tf32(v.w));
            *reinterpret_cast<float4*>(g_W2 + idx) = o;
        }
    } else {
        int idx = ((bid - nb1) * 256 + threadIdx.x) * 4;
        if (idx < total) {
            int i1 = srows * ip[0] + 1;
            int d = idx % D;
            int r = (idx / D) % srows;
            int b = idx / (D * srows);
            float4 v;
            if (r == i1)
                v = *reinterpret_cast<const float4*>(x + ((size_t)b * S + (S - 1)) * D + d);
            else
                v = *reinterpret_cast<const float4*>(state + idx);
            *reinterpret_cast<float4*>(outs + idx) = v;
        }
    }
}

extern "C" void kernel_launch(void* const* d_in, const int* in_sizes, int n_in,
                              void* d_out, int out_size)
{
    const float* x     = (const float*)d_in[0];
    const float* state = (const float*)d_in[1];
    const float* tmx   = (const float*)d_in[2];
    const float* w1    = (const float*)d_in[3];
    const float* w2    = (const float*)d_in[4];
    const float* mk    = (const float*)d_in[5];
    const float* mw    = (const float*)d_in[6];
    const float* mv    = (const float*)d_in[7];
    const float* mr    = (const float*)d_in[8];
    const float* mg    = (const float*)d_in[9];
    const int*   ip    = (const int*)d_in[10];
    float* out = (float*)d_out;

    const int D     = in_sizes[2];
    const int srows = 2 + D / 32;
    const int Bb    = in_sizes[1] / (srows * D);
    const int M     = in_sizes[0] / D;
    const int S     = M / Bb;
    const int n1    = in_sizes[3];
    const int n2    = in_sizes[4];

    static bool attr_done = false;
    if (!attr_done) {
        cudaFuncSetAttribute(gemm1_kernel, cudaFuncAttributeMaxDynamicSharedMemorySize, G1_SMEM);
        cudaFuncSetAttribute(gemm2_kernel, cudaFuncAttributeMaxDynamicSharedMemorySize, G2_SMEM);
        attr_done = true;
    }

    long long main_sz = (long long)M * 5 * D;
    long long st_sz   = (long long)Bb * srows * D;
    int total = ((long long)out_size >= main_sz + st_sz) ? (int)st_sz : 0;

    int nmax = n1 > n2 ? n1 : n2;
    int nb1 = (nmax / 4 + 255) / 256;
    int nb2 = (total / 4 + 255) / 256;
    prep_kernel<<<nb1 + nb2, 256>>>(w1, w2, x, state, ip, out + main_sz,
                                    n1, n2, nb1, S, D, srows, total);
    gemm1_kernel<<<M / 64, 512, G1_SMEM>>>(x, state, tmx, ip, S, D, srows);
    gemm2_kernel<<<dim3(M / 64, D / 128), 256, G2_SMEM>>>(x, state, mk, mw, mv, mr, mg,
                                                          ip, out, S, D, srows);
}

// round 8
// speedup vs baseline: 1.1457x; 1.0020x over previous
#include <cuda_runtime.h>
#include <cstdint>
#include <cstddef>

// ---------------- scratch ----------------
__device__ float g_W1[2048 * 160];      // tf32-rounded w1
__device__ float g_W2[5 * 32 * 2048];   // tf32-rounded w2
__device__ float g_H[8192 * 160];       // tanh(xx@W1), tf32-rounded

__device__ __forceinline__ unsigned f2tf32(float f) {
    unsigned u;
    asm("cvt.rna.tf32.f32 %0, %1;" : "=r"(u) : "f"(f));
    return u;
}

__device__ __forceinline__ void mma_tf32(float c[4], const unsigned a[4],
                                         unsigned b0, unsigned b1) {
    asm volatile(
        "mma.sync.aligned.m16n8k8.row.col.f32.tf32.tf32.f32 "
        "{%0,%1,%2,%3}, {%4,%5,%6,%7}, {%8,%9}, {%0,%1,%2,%3};\n"
        : "+f"(c[0]), "+f"(c[1]), "+f"(c[2]), "+f"(c[3])
        : "r"(a[0]), "r"(a[1]), "r"(a[2]), "r"(a[3]), "r"(b0), "r"(b1));
}

__device__ __forceinline__ void cp16(uint32_t dst, const void* src) {
    asm volatile("cp.async.cg.shared.global [%0], [%1], 16;\n" :: "r"(dst), "l"(src));
}
__device__ __forceinline__ void cp_commit() { asm volatile("cp.async.commit_group;\n"); }
__device__ __forceinline__ void cp_wait0()  { asm volatile("cp.async.wait_group 0;\n" ::: "memory"); }
__device__ __forceinline__ void cp_wait1()  { asm volatile("cp.async.wait_group 1;\n" ::: "memory"); }

__device__ __forceinline__ uint32_t smem_u32(const void* p) {
    return (uint32_t)__cvta_generic_to_shared(p);
}

// ============================================================================
// GEMM1: H[M,160] = tanh( (x + sx*tmx) @ W1[D,160] )   (unchanged from R7)
// 512 threads, 16 warps 4(m)x4(n), block tile 64x160, 3-stage cp.async ring.
// ============================================================================
#define G1_AS   18432                    // 2*64*36*4
#define G1_BS   64512                    // 3*32*168*4
#define G1_XS   28080                    // 3*65*36*4
#define G1_TMX  8192
#define G1_SMEM (G1_AS + G1_BS + G1_XS + G1_TMX)

__global__ void __launch_bounds__(512)
gemm1_kernel(const float* __restrict__ x, const float* __restrict__ state,
             const float* __restrict__ tmx,
             const int* __restrict__ ip, int S, int D, int srows)
{
    extern __shared__ unsigned char sm[];
    unsigned (*As)[64][36]   = reinterpret_cast<unsigned (*)[64][36]>(sm);
    unsigned (*Bs1)[32][168] = reinterpret_cast<unsigned (*)[32][168]>(sm + G1_AS);
    float    (*Xs)[65][36]   = reinterpret_cast<float (*)[65][36]>(sm + G1_AS + G1_BS);
    float*    tmxs           = reinterpret_cast<float*>(sm + G1_AS + G1_BS + G1_XS);

    const int tid  = threadIdx.x;
    const int lane = tid & 31;
    const int warp = tid >> 5;
    const int wm   = warp & 3;
    const int wn   = warp >> 2;
    const int gid  = lane >> 2;
    const int tg   = lane & 3;
    const int m0   = blockIdx.x * 64;
    const int i1   = srows * ip[0] + 1;

    const float* xprow0 = ((m0 % S) == 0)
        ? state + ((size_t)(m0 / S) * srows + i1) * D
        : x + (size_t)(m0 - 1) * D;

    auto issueX1 = [&](int s) {
        int k0 = s * 32, slot = s % 3;
        {
            int r = tid >> 3, cg = (tid & 7) * 4;
            const float* src = (r == 0) ? xprow0 + k0 + cg
                                        : x + (size_t)(m0 - 1 + r) * D + k0 + cg;
            cp16(smem_u32(&Xs[slot][r][cg]), src);
        }
        if (tid < 8) {
            int cg = tid * 4;
            cp16(smem_u32(&Xs[slot][64][cg]), x + (size_t)(m0 + 63) * D + k0 + cg);
        }
    };
    auto issueB1 = [&](int s) {
        int k0 = s * 32, slot = s % 3;
        #pragma unroll
        for (int it = 0; it < 3; it++) {
            int e = tid + it * 512;
            if (e < 1280) {
                int r = e / 40, c4 = (e % 40) * 4;
                cp16(smem_u32(&Bs1[slot][r][c4]), g_W1 + (size_t)(k0 + r) * 160 + c4);
            }
        }
    };

    if (tid < D / 4) cp16(smem_u32(tmxs + tid * 4), tmx + tid * 4);
    issueX1(0); issueB1(0); cp_commit();
    issueX1(1); issueB1(1); cp_commit();

    float acc1[5][4];
    #pragma unroll
    for (int b = 0; b < 5; b++)
        #pragma unroll
        for (int c = 0; c < 4; c++) acc1[b][c] = 0.f;

    const int nkt = D / 32;
    for (int kt = 0; kt < nkt; kt++) {
        const int slot = kt % 3, buf = kt & 1, k0 = kt * 32;
        if (kt + 1 < nkt) cp_wait1(); else cp_wait0();
        __syncthreads();
        if (kt + 2 < nkt) { issueX1(kt + 2); issueB1(kt + 2); cp_commit(); }

        {
            int r = tid >> 3, c4 = (tid & 7) * 4;
            float4 xv = *reinterpret_cast<float4*>(&Xs[slot][r + 1][c4]);
            float4 xp = *reinterpret_cast<float4*>(&Xs[slot][r][c4]);
            float4 tv = *reinterpret_cast<float4*>(&tmxs[k0 + c4]);
            uint4 o;
            o.x = f2tf32(xv.x + (xp.x - xv.x) * tv.x);
            o.y = f2tf32(xv.y + (xp.y - xv.y) * tv.y);
            o.z = f2tf32(xv.z + (xp.z - xv.z) * tv.z);
            o.w = f2tf32(xv.w + (xp.w - xv.w) * tv.w);
            *reinterpret_cast<uint4*>(&As[buf][r][c4]) = o;
        }
        __syncthreads();

        #pragma unroll
        for (int kk = 0; kk < 4; kk++) {
            unsigned a[4];
            int ar = wm * 16 + gid;
            int ac = kk * 8 + tg;
            a[0] = As[buf][ar][ac];
            a[1] = As[buf][ar + 8][ac];
            a[2] = As[buf][ar][ac + 4];
            a[3] = As[buf][ar + 8][ac + 4];
            #pragma unroll
            for (int nt = 0; nt < 5; nt++) {
                int bc = wn * 40 + nt * 8 + gid;
                unsigned b0 = Bs1[slot][kk * 8 + tg][bc];
                unsigned b1 = Bs1[slot][kk * 8 + tg + 4][bc];
                mma_tf32(acc1[nt], a, b0, b1);
            }
        }
    }

    #pragma unroll
    for (int nt = 0; nt < 5; nt++) {
        int gc = wn * 40 + nt * 8 + 2 * tg;
        #pragma unroll
        for (int h = 0; h < 2; h++) {
            int gr = m0 + wm * 16 + gid + h * 8;
            float2 v;
            v.x = __uint_as_float(f2tf32(tanhf(acc1[nt][2 * h])));
            v.y = __uint_as_float(f2tf32(tanhf(acc1[nt][2 * h + 1])));
            *reinterpret_cast<float2*>(g_H + (size_t)gr * 160 + gc) = v;
        }
    }
}

// ============================================================================
// GEMM2 + epilogue. Tile 64m x 64n, 5 modes inner, H-slice + W2 double-buffered.
// 256 threads, 54.5 KB smem -> 4 CTAs/SM (32 warps).
// Warps: 2(m) x 4(n); warp tile 32m x 16n.
// ============================================================================
#define G2_HS   18432                    // 2*64*36*4
#define G2_BS   18432                    // 2*32*72*4
#define G2_XV   17680                    // 65*68*4
#define G2_SMEM (G2_HS + G2_BS + G2_XV)

__global__ void __launch_bounds__(256, 4)
gemm2_kernel(const float* __restrict__ x, const float* __restrict__ state,
             const float* __restrict__ mk, const float* __restrict__ mw,
             const float* __restrict__ mv, const float* __restrict__ mr,
             const float* __restrict__ mg,
             const int* __restrict__ ip, float* __restrict__ out,
             int S, int D, int srows)
{
    extern __shared__ unsigned char sm[];
    unsigned (*Hs)[64][36] = reinterpret_cast<unsigned (*)[64][36]>(sm);
    unsigned (*Bs)[32][72] = reinterpret_cast<unsigned (*)[32][72]>(sm + G2_HS);
    float    (*Xv)[68]     = reinterpret_cast<float (*)[68]>(sm + G2_HS + G2_BS);

    const int tid  = threadIdx.x;
    const int lane = tid & 31;
    const int warp = tid >> 5;
    const int wm   = warp & 1;     // m: wm*32
    const int wn   = warp >> 1;    // n: wn*16
    const int gid  = lane >> 2;
    const int tg   = lane & 3;
    const int n0   = blockIdx.x * 64;
    const int m0   = blockIdx.y * 64;
    const int i1   = srows * ip[0] + 1;

    const float* xprow0 = ((m0 % S) == 0)
        ? state + ((size_t)(m0 / S) * srows + i1) * D
        : x + (size_t)(m0 - 1) * D;

    auto issueH = [&](int f, int buf) {
        #pragma unroll
        for (int it = 0; it < 2; it++) {
            int e = tid + it * 256;
            int r = e >> 3, c4 = (e & 7) * 4;
            cp16(smem_u32(&Hs[buf][r][c4]),
                 g_H + (size_t)(m0 + r) * 160 + f * 32 + c4);
        }
    };
    auto issueB = [&](int f, int buf) {
        #pragma unroll
        for (int it = 0; it < 2; it++) {
            int e = tid + it * 256;
            int r = e >> 4, c4 = (e & 15) * 4;
            cp16(smem_u32(&Bs[buf][r][c4]),
                 g_W2 + ((size_t)f * 32 + r) * D + n0 + c4);
        }
    };

    // prologue: Xv + (H,B) for f=0 | (H,B) for f=1
    #pragma unroll
    for (int it = 0; it < 5; it++) {
        int u = tid + it * 256;
        if (u < 1040) {
            int r = u >> 4, cg = (u & 15) * 4;
            const float* src = (r == 0) ? xprow0 + n0 + cg
                                        : x + (size_t)(m0 - 1 + r) * D + n0 + cg;
            cp16(smem_u32(&Xv[r][cg]), src);
        }
    }
    issueH(0, 0); issueB(0, 0); cp_commit();
    issueH(1, 1); issueB(1, 1); cp_commit();

    #pragma unroll
    for (int f = 0; f < 5; f++) {
        const int buf = f & 1;
        if (f < 4) cp_wait1(); else cp_wait0();
        __syncthreads();

        float acc[2][2][4];
        #pragma unroll
        for (int a = 0; a < 2; a++)
            #pragma unroll
            for (int b = 0; b < 2; b++)
                #pragma unroll
                for (int c = 0; c < 4; c++) acc[a][b][c] = 0.f;

        #pragma unroll
        for (int kk = 0; kk < 4; kk++) {
            unsigned a[2][4];
            #pragma unroll
            for (int mi = 0; mi < 2; mi++) {
                int ar = wm * 32 + mi * 16 + gid;
                int ac = kk * 8 + tg;
                a[mi][0] = Hs[buf][ar][ac];
                a[mi][1] = Hs[buf][ar + 8][ac];
                a[mi][2] = Hs[buf][ar][ac + 4];
                a[mi][3] = Hs[buf][ar + 8][ac + 4];
            }
            #pragma unroll
            for (int nt = 0; nt < 2; nt++) {
                int bc = wn * 16 + nt * 8 + gid;
                unsigned b0 = Bs[buf][kk * 8 + tg][bc];
                unsigned b1 = Bs[buf][kk * 8 + tg + 4][bc];
                mma_tf32(acc[0][nt], a[0], b0, b1);
                mma_tf32(acc[1][nt], a[1], b0, b1);
            }
        }
        __syncthreads();                 // done reading Hs/Bs[buf]
        if (f + 2 <= 4) {                // refill this buffer for mode f+2
            issueH(f + 2, buf);
            issueB(f + 2, buf);
            cp_commit();
        }

        const float* maa = (f == 0) ? mk : (f == 1) ? mw : (f == 2) ? mv
                         : (f == 3) ? mr : mg;

        #pragma unroll
        for (int mi = 0; mi < 2; mi++)
            #pragma unroll
            for (int nt = 0; nt < 2; nt++) {
                int lc = wn * 16 + nt * 8 + 2 * tg;
                int gc = n0 + lc;
                float2 mm = *reinterpret_cast<const float2*>(maa + gc);
                #pragma unroll
                for (int h = 0; h < 2; h++) {
                    int lr = wm * 32 + mi * 16 + gid + h * 8;
                    float2 xv = *reinterpret_cast<float2*>(&Xv[lr + 1][lc]);
                    float2 xp = *reinterpret_cast<float2*>(&Xv[lr][lc]);
                    float y0 = acc[mi][nt][2 * h];
                    float y1 = acc[mi][nt][2 * h + 1];
                    float2 o;
                    o.x = xv.x + (xp.x - xv.x) * (mm.x + y0);
                    o.y = xv.y + (xp.y - xv.y) * (mm.y + y1);
                    __stcs(reinterpret_cast<float2*>(
                        out + ((size_t)(m0 + lr) * 5 + f) * D + gc), o);
                }
            }
    }
}

// ---------------------------------------------------------------------------
// prep kernel: tf32-round W1/W2 + build new_state
// ---------------------------------------------------------------------------
__global__ void prep_kernel(const float* __restrict__ w1, const float* __restrict__ w2,
                            const float* __restrict__ x, const float* __restrict__ state,
                            const int* __restrict__ ip, float* __restrict__ outs,
                            int n1, int n2, int nb1, int S, int D, int srows, int total)
{
    int bid = blockIdx.x;
    if (bid < nb1) {
        int idx = (bid * 256 + threadIdx.x) * 4;
        if (idx < n1) {
            float4 v = *reinterpret_cast<const float4*>(w1 + idx);
            float4 o;
            o.x = __uint_as_float(f2tf32(v.x)); o.y = __uint_as_float(f2tf32(v.y));
            o.z = __uint_as_float(f2tf32(v.z)); o.w = __uint_as_float(f2tf32(v.w));
            *reinterpret_cast<float4*>(g_W1 + idx) = o;
        }
        if (idx < n2) {
            float4 v = *reinterpret_cast<const float4*>(w2 + idx);
            float4 o;
            o.x = __uint_as_float(f2tf32(v.x)); o.y = __uint_as_float(f2tf32(v.y));
            o.z = __uint_as_float(f2tf32(v.z)); o.w = __uint_as_float(f2tf32(v.w));
            *reinterpret_cast<float4*>(g_W2 + idx) = o;
        }
    } else {
        int idx = ((bid - nb1) * 256 + threadIdx.x) * 4;
        if (idx < total) {
            int i1 = srows * ip[0] + 1;
            int d = idx % D;
            int r = (idx / D) % srows;
            int b = idx / (D * srows);
            float4 v;
            if (r == i1)
                v = *reinterpret_cast<const float4*>(x + ((size_t)b * S + (S - 1)) * D + d);
            else
                v = *reinterpret_cast<const float4*>(state + idx);
            *reinterpret_cast<float4*>(outs + idx) = v;
        }
    }
}

extern "C" void kernel_launch(void* const* d_in, const int* in_sizes, int n_in,
                              void* d_out, int out_size)
{
    const float* x     = (const float*)d_in[0];
    const float* state = (const float*)d_in[1];
    const float* tmx   = (const float*)d_in[2];
    const float* w1    = (const float*)d_in[3];
    const float* w2    = (const float*)d_in[4];
    const float* mk    = (const float*)d_in[5];
    const float* mw    = (const float*)d_in[6];
    const float* mv    = (const float*)d_in[7];
    const float* mr    = (const float*)d_in[8];
    const float* mg    = (const float*)d_in[9];
    const int*   ip    = (const int*)d_in[10];
    float* out = (float*)d_out;

    const int D     = in_sizes[2];
    const int srows = 2 + D / 32;
    const int Bb    = in_sizes[1] / (srows * D);
    const int M     = in_sizes[0] / D;
    const int S     = M / Bb;
    const int n1    = in_sizes[3];
    const int n2    = in_sizes[4];

    static bool attr_done = false;
    if (!attr_done) {
        cudaFuncSetAttribute(gemm1_kernel, cudaFuncAttributeMaxDynamicSharedMemorySize, G1_SMEM);
        cudaFuncSetAttribute(gemm2_kernel, cudaFuncAttributeMaxDynamicSharedMemorySize, G2_SMEM);
        attr_done = true;
    }

    long long main_sz = (long long)M * 5 * D;
    long long st_sz   = (long long)Bb * srows * D;
    int total = ((long long)out_size >= main_sz + st_sz) ? (int)st_sz : 0;

    int nmax = n1 > n2 ? n1 : n2;
    int nb1 = (nmax / 4 + 255) / 256;
    int nb2 = (total / 4 + 255) / 256;
    prep_kernel<<<nb1 + nb2, 256>>>(w1, w2, x, state, ip, out + main_sz,
                                    n1, n2, nb1, S, D, srows, total);
    gemm1_kernel<<<M / 64, 512, G1_SMEM>>>(x, state, tmx, ip, S, D, srows);
    gemm2_kernel<<<dim3(D / 64, M / 64), 256, G2_SMEM>>>(x, state, mk, mw, mv, mr, mg,
                                                         ip, out, S, D, srows);
}